// round 16
// baseline (speedup 1.0000x reference)
#include <cuda_runtime.h>
#include <cuda_fp16.h>
#include <mma.h>
#include <cstdint>

using namespace nvcuda;

#define BSZ 128
#define TN  512
#define UN  1024
#define MROWS (TN * BSZ)   // 65536
#define NCTA 128

// ---------------- scratch (static device globals) ----------------
__device__ __half g_Xh [(size_t)MROWS * UN];
__device__ __half g_Eh [(size_t)MROWS * UN];
__device__ float  g_ZK [(size_t)MROWS * 4 * UN];   // permuted cols p=u*4+g
__device__ float  g_C  [(size_t)BSZ * UN];
__device__ __half g_Hhi[(size_t)(TN + 1) * BSZ * UN];
__device__ __half g_Wemb[(size_t)UN * UN];
__device__ __half g_Wout[(size_t)UN * UN];
__device__ __half g_Wk  [(size_t)UN * 4 * UN];     // permuted cols
__device__ __half g_Wr  [(size_t)UN * 4 * UN];     // permuted cols
__device__ int    g_count;

struct __align__(8) H4 { __half v[4]; };

__device__ __forceinline__ void cp16(uint32_t dst, const void* src) {
    asm volatile("cp.async.cg.shared.global [%0], [%1], 16;" :: "r"(dst), "l"(src));
}
__device__ __forceinline__ void cp_commit() { asm volatile("cp.async.commit_group;"); }
template<int N> __device__ __forceinline__ void cp_wait() {
    asm volatile("cp.async.wait_group %0;" :: "n"(N));
}

// ---------------- merged prep kernel ----------------
// [0,16384) X->fp16 (16 elems/thread) | [16384,16896) init_state |
// [16896,17920) W_emb | [17920,18944) W_out | [18944,23040) W_k perm | [23040,27136) W_r perm
#define PREP_ST0   16384
#define PREP_WE0   16896
#define PREP_WO0   17920
#define PREP_WK0   18944
#define PREP_WR0   23040
#define PREP_BLOCKS 27136

__global__ __launch_bounds__(256) void prep_all(
    const float* __restrict__ X, const float* __restrict__ h0, const float* __restrict__ c0,
    const float* __restrict__ W_emb, const float* __restrict__ W_out,
    const float* __restrict__ W_k, const float* __restrict__ W_r)
{
    const int b = blockIdx.x, tid = threadIdx.x;
    if (b < PREP_ST0) {                    // X -> fp16, 16 elems/thread
        size_t e = ((size_t)b * 256 + tid) * 16;
        size_t r = e >> 10;
        int k = (int)(e & 1023);
        int bb = (int)(r & 127), t = (int)(r >> 7);
        const float* src = X + ((size_t)bb * 513 + (size_t)t) * 1024 + k;
        float4 v0 = *(const float4*)(src);
        float4 v1 = *(const float4*)(src + 4);
        float4 v2 = *(const float4*)(src + 8);
        float4 v3 = *(const float4*)(src + 12);
        H4 h[4];
        h[0].v[0] = __float2half_rn(v0.x); h[0].v[1] = __float2half_rn(v0.y);
        h[0].v[2] = __float2half_rn(v0.z); h[0].v[3] = __float2half_rn(v0.w);
        h[1].v[0] = __float2half_rn(v1.x); h[1].v[1] = __float2half_rn(v1.y);
        h[1].v[2] = __float2half_rn(v1.z); h[1].v[3] = __float2half_rn(v1.w);
        h[2].v[0] = __float2half_rn(v2.x); h[2].v[1] = __float2half_rn(v2.y);
        h[2].v[2] = __float2half_rn(v2.z); h[2].v[3] = __float2half_rn(v2.w);
        h[3].v[0] = __float2half_rn(v3.x); h[3].v[1] = __float2half_rn(v3.y);
        h[3].v[2] = __float2half_rn(v3.z); h[3].v[3] = __float2half_rn(v3.w);
        *(int4*)(g_Xh + e)     = *(int4*)&h[0];
        *(int4*)(g_Xh + e + 8) = *(int4*)&h[2];
    } else if (b < PREP_WE0) {             // init_state
        int i = (b - PREP_ST0) * 256 + tid;
        if (b == PREP_ST0 && tid == 0) g_count = 0;
        g_C[i] = c0[i];
        g_Hhi[i] = __float2half_rn(h0[i]);
    } else if (b < PREP_WK0) {             // W_emb / W_out -> fp16
        int isout = (b >= PREP_WO0);
        const float* W = isout ? W_out : W_emb;
        __half* dst = isout ? g_Wout : g_Wemb;
        size_t q = (size_t)(b - (isout ? PREP_WO0 : PREP_WE0)) * 256 + tid;
        size_t e = q * 4;
        float4 v = *(const float4*)(W + e);
        H4 h;
        h.v[0] = __float2half_rn(v.x); h.v[1] = __float2half_rn(v.y);
        h.v[2] = __float2half_rn(v.z); h.v[3] = __float2half_rn(v.w);
        *(H4*)(dst + e) = h;
    } else {                               // W_k / W_r permuted -> fp16
        int isr = (b >= PREP_WR0);
        const float* W = isr ? W_r : W_k;
        __half* dst = isr ? g_Wr : g_Wk;
        size_t q = (size_t)(b - (isr ? PREP_WR0 : PREP_WK0)) * 256 + tid;
        int row = (int)(q >> 10);
        int qc = (int)(q & 1023);
        const float* src = W + (size_t)row * 4096 + qc;
        H4 h;
        h.v[0] = __float2half_rn(src[0]);
        h.v[1] = __float2half_rn(src[1024]);
        h.v[2] = __float2half_rn(src[2048]);
        h.v[3] = __float2half_rn(src[3072]);
        *(H4*)(dst + (size_t)row * 4096 + (size_t)qc * 4) = h;
    }
}

// ---------------- fp16 1-term wmma GEMM, 2-buffer cp.async pipeline (unchanged) ----------------
#define WG_BUF   18944
#define WG_BIAS  37888
#define WG_TOTAL 46080

__global__ __launch_bounds__(256) void wgemm(
    const __half* __restrict__ A, const __half* __restrict__ B,
    const float* __restrict__ bias, float* __restrict__ D,
    __half* __restrict__ Dh,
    int N, int mode)
{
    extern __shared__ char sm[];
    const uint32_t smb = (uint32_t)__cvta_generic_to_shared(sm);

    const int tid = threadIdx.x;
    const int n0 = blockIdx.x * 128, m0 = blockIdx.y * 128;
    const int wid = tid >> 5, lane = tid & 31;
    const int wm = wid & 3, wn = wid >> 2;

    float (*sbias)[128] = (float (*)[128])(sm + WG_BIAS);
    for (int i = tid; i < 2048; i += 256) {
        int col = i & 127;
        int p = n0 + col;
        float bv = (mode == 1) ? bias[(p & 3) * 1024 + (p >> 2)] : bias[p];
        sbias[i >> 7][col] = bv;
    }
    __syncthreads();

    wmma::fragment<wmma::accumulator, 16, 16, 16, float> acc[2][4];
#pragma unroll
    for (int i = 0; i < 2; i++)
#pragma unroll
        for (int j = 0; j < 4; j++)
            wmma::load_matrix_sync(acc[i][j], &sbias[0][wn * 64 + j * 16], 128, wmma::mem_row_major);
    __syncthreads();

    const int arow = tid >> 1, aseg = (tid & 1) * 16;
    const int brow = tid >> 3, bseg = (tid & 7) * 16;

    auto issue = [&](int c) {
        uint32_t base = smb + (uint32_t)(c & 1) * WG_BUF;
        int k0 = c * 32;
        uint32_t ad = base + (uint32_t)(arow * 40 + aseg) * 2;
        const __half* ap = A + (size_t)(m0 + arow) * 1024 + k0 + aseg;
        cp16(ad,      ap);
        cp16(ad + 16, ap + 8);
        uint32_t bd = base + 10240 + (uint32_t)(brow * 136 + bseg) * 2;
        const __half* bp = B + (size_t)(k0 + brow) * N + n0 + bseg;
        cp16(bd,      bp);
        cp16(bd + 16, bp + 8);
        cp_commit();
    };

    issue(0);
    for (int c = 0; c < 32; c++) {
        cp_wait<0>();
        __syncthreads();
        if (c + 1 < 32) issue(c + 1);

        char* bufp = sm + (c & 1) * WG_BUF;
        __half (*sA)[40]  = (__half (*)[40])(bufp);
        __half (*sB)[136] = (__half (*)[136])(bufp + 10240);

#pragma unroll
        for (int kk = 0; kk < 32; kk += 16) {
            wmma::fragment<wmma::matrix_a, 16, 16, 16, __half, wmma::row_major> ah[2];
            wmma::fragment<wmma::matrix_b, 16, 16, 16, __half, wmma::row_major> bh[4];
#pragma unroll
            for (int i = 0; i < 2; i++)
                wmma::load_matrix_sync(ah[i], &sA[wm * 32 + i * 16][kk], 40);
#pragma unroll
            for (int j = 0; j < 4; j++)
                wmma::load_matrix_sync(bh[j], &sB[kk][wn * 64 + j * 16], 136);
#pragma unroll
            for (int i = 0; i < 2; i++)
#pragma unroll
                for (int j = 0; j < 4; j++)
                    wmma::mma_sync(acc[i][j], ah[i], bh[j], acc[i][j]);
        }
    }

    if (mode == 0) {
        float (*stage)[16] = (float (*)[16])((float*)(sm + WG_BIAS) + wid * 256);
        __syncthreads();
#pragma unroll
        for (int i = 0; i < 2; i++)
#pragma unroll
            for (int j = 0; j < 4; j++) {
                for (int e = 0; e < acc[i][j].num_elements; e++)
                    acc[i][j].x[e] = fmaxf(acc[i][j].x[e], 0.f);
                wmma::store_matrix_sync(&stage[0][0], acc[i][j], 16, wmma::mem_row_major);
                __syncwarp();
                int r = lane & 15, c8 = (lane >> 4) * 8;
                size_t row = (size_t)(m0 + wm * 32 + i * 16 + r);
                size_t off = row * 1024 + (n0 + wn * 64 + j * 16 + c8);
                H4 h0v, h1v;
#pragma unroll
                for (int e = 0; e < 4; e++) h0v.v[e] = __float2half_rn(stage[r][c8 + e]);
#pragma unroll
                for (int e = 0; e < 4; e++) h1v.v[e] = __float2half_rn(stage[r][c8 + 4 + e]);
                *(H4*)(Dh + off)     = h0v;
                *(H4*)(Dh + off + 4) = h1v;
                __syncwarp();
            }
        return;
    }

#pragma unroll
    for (int i = 0; i < 2; i++)
#pragma unroll
        for (int j = 0; j < 4; j++) {
            int col = n0 + wn * 64 + j * 16;
            if (mode == 2) {
                int t = m0 >> 7;
                int b = wm * 32 + i * 16;
                float* p = D + (size_t)t * 1024 + (size_t)b * ((size_t)TN * 1024) + col;
                wmma::store_matrix_sync(p, acc[i][j], (unsigned)(TN * 1024), wmma::mem_row_major);
            } else {
                int row = m0 + wm * 32 + i * 16;
                wmma::store_matrix_sync(D + (size_t)row * N + col, acc[i][j], N, wmma::mem_row_major);
            }
        }
}

// ---------------- persistent recurrence: fp16 1-term, K-chunk 128, W in SMEM ----------------
// 128 CTAs x 512 thr. SMEM: WH[1024][40] 80K | A: 3 bufs x 34816 ([128][136] fp16).
// 16 warps: (wm 0..3 = M32) x (wn 0..1 = N16) x (g 0..1 = K-half of 128-chunk, 4 sub-k each).
// 8 chunk iterations/step (halved sync overhead vs chunk-64).
#define PS_WH 0
#define PS_A  81920
#define PS_ABUF 34816
#define PS_TOTAL (81920 + 3 * PS_ABUF)    // 186368

__global__ __launch_bounds__(512, 1) void lstm_persist7(const __half* __restrict__ W_g)
{
    extern __shared__ char sm[];
    const uint32_t smb = (uint32_t)__cvta_generic_to_shared(sm);
    const int tid = threadIdx.x, wid = tid >> 5;
    const int bx = blockIdx.x;
    const int n0g = bx * 32;
    const int g = wid >> 3, w8 = wid & 7;
    const int wm = w8 >> 1, wn = w8 & 1;

    for (int i = tid; i < 4096; i += 512) {
        int row = i >> 2, seg = (i & 3) * 8;
        cp16(smb + PS_WH + (uint32_t)(row * 40 + seg) * 2, W_g + (size_t)row * 4096 + n0g + seg);
    }
    cp_commit(); cp_wait<0>();
    __syncthreads();

    __half (*WH)[40] = (__half (*)[40])(sm + PS_WH);

    const int m = tid & 127, grp = tid >> 7;
    const int pc = grp * 8;
    float cv[2];
    {
        float2 c2 = *(const float2*)(g_C + (size_t)m * UN + bx * 8 + grp * 2);
        cv[0] = c2.x; cv[1] = c2.y;
    }
    // A cp.async: chunk = 128 rows x 128 halves = 32KB; 512 thr x 4 cp16 (32 halves each)
    const int arow = tid >> 2, aseg = (tid & 3) * 32;

    for (int t = 0; t < TN; t++) {
        const __half* __restrict__ Hhi = g_Hhi + (size_t)t * (BSZ * UN);

        float zkf[8];
        {
            const float* zk = g_ZK + ((size_t)t * BSZ + m) * 4096 + n0g + pc;
            float4 v0 = *(const float4*)(zk);
            float4 v1 = *(const float4*)(zk + 4);
            zkf[0] = v0.x; zkf[1] = v0.y; zkf[2] = v0.z; zkf[3] = v0.w;
            zkf[4] = v1.x; zkf[5] = v1.y; zkf[6] = v1.z; zkf[7] = v1.w;
        }

        auto issueA = [&](int chunk) {
            int buf = chunk % 3;
            uint32_t ad = smb + PS_A + buf * PS_ABUF + (uint32_t)(arow * 136 + aseg) * 2;
            const __half* src = Hhi + (size_t)arow * 1024 + chunk * 128 + aseg;
            cp16(ad,      src);
            cp16(ad + 16, src + 8);
            cp16(ad + 32, src + 16);
            cp16(ad + 48, src + 24);
            cp_commit();
        };

        wmma::fragment<wmma::accumulator, 16, 16, 16, float> a0[2];
        wmma::fill_fragment(a0[0], 0.f);
        wmma::fill_fragment(a0[1], 0.f);

        issueA(0); issueA(1);
        for (int c = 0; c < 8; c++) {
            if (c < 7) cp_wait<1>(); else cp_wait<0>();
            __syncthreads();
            if (c + 2 < 8) issueA(c + 2);

            int buf = c % 3;
            __half (*Ah)[136] = (__half (*)[136])(sm + PS_A + buf * PS_ABUF);

#pragma unroll
            for (int s = 0; s < 4; s++) {
                const int kkg = c * 128 + g * 64 + s * 16;   // W row
                const int ka  = g * 64 + s * 16;             // A col
                wmma::fragment<wmma::matrix_b, 16, 16, 16, __half, wmma::row_major> bh;
                wmma::fragment<wmma::matrix_a, 16, 16, 16, __half, wmma::row_major> ah0, ah1;
                wmma::load_matrix_sync(bh, &WH[kkg][wn * 16], 40);
                wmma::load_matrix_sync(ah0, &Ah[wm * 32][ka], 136);
                wmma::load_matrix_sync(ah1, &Ah[wm * 32 + 16][ka], 136);
                wmma::mma_sync(a0[0], ah0, bh, a0[0]);
                wmma::mma_sync(a0[1], ah1, bh, a0[1]);
            }
        }

        // partial z per K-group -> two smem buffers (overlay A buffers, now dead)
        __syncthreads();
        float (*zp)[36] = (float (*)[36])(sm + PS_A + g * 18432);
#pragma unroll
        for (int i = 0; i < 2; i++)
            wmma::store_matrix_sync(&zp[wm * 32 + i * 16][wn * 16], a0[i], 36, wmma::mem_row_major);
        __syncthreads();

        float (*z0)[36] = (float (*)[36])(sm + PS_A);
        float (*z1)[36] = (float (*)[36])(sm + PS_A + 18432);
        __half2 hh2;
#pragma unroll
        for (int e = 0; e < 2; e++) {
            float zi = z0[m][pc + e * 4 + 0] + z1[m][pc + e * 4 + 0] + zkf[e * 4 + 0];
            float zf = z0[m][pc + e * 4 + 1] + z1[m][pc + e * 4 + 1] + zkf[e * 4 + 1];
            float zg = z0[m][pc + e * 4 + 2] + z1[m][pc + e * 4 + 2] + zkf[e * 4 + 2];
            float zo = z0[m][pc + e * 4 + 3] + z1[m][pc + e * 4 + 3] + zkf[e * 4 + 3];
            float si = 1.f / (1.f + __expf(-zi));
            float sf = 1.f / (1.f + __expf(-zf));
            float so = 1.f / (1.f + __expf(-zo));
            float cn = sf * cv[e] + si * tanhf(zg);
            float hn = so * tanhf(cn);
            cv[e] = cn;
            __half h = __float2half_rn(hn);
            if (e == 0) hh2.x = h; else hh2.y = h;
        }
        size_t ho = (size_t)(t + 1) * (BSZ * UN) + (size_t)m * UN + bx * 8 + grp * 2;
        *(__half2*)(g_Hhi + ho) = hh2;

        __threadfence();
        __syncthreads();
        if (tid == 0) {
            atomicAdd(&g_count, 1);
            volatile int* gc = &g_count;
            int target = NCTA * (t + 1);
            while (*gc < target) __nanosleep(64);
        }
        __syncthreads();
    }
}

// ---------------- host ----------------
extern "C" void kernel_launch(void* const* d_in, const int* in_sizes, int n_in,
                              void* d_out, int out_size)
{
    const float* h0    = (const float*)d_in[0];
    const float* c0    = (const float*)d_in[1];
    const float* X     = (const float*)d_in[2];
    const float* W_emb = (const float*)d_in[3];
    const float* b_emb = (const float*)d_in[4];
    const float* W_k   = (const float*)d_in[5];
    const float* W_r   = (const float*)d_in[6];
    const float* b_r   = (const float*)d_in[7];
    const float* W_out = (const float*)d_in[8];
    const float* b_out = (const float*)d_in[9];
    (void)in_sizes; (void)n_in; (void)out_size;

    __half *pXh, *pEh, *pHhi, *pWemb, *pWout, *pWk, *pWr;
    float *pZK;
    cudaGetSymbolAddress((void**)&pXh, g_Xh);
    cudaGetSymbolAddress((void**)&pEh, g_Eh);
    cudaGetSymbolAddress((void**)&pHhi, g_Hhi);
    cudaGetSymbolAddress((void**)&pWemb, g_Wemb);
    cudaGetSymbolAddress((void**)&pWout, g_Wout);
    cudaGetSymbolAddress((void**)&pWk, g_Wk);
    cudaGetSymbolAddress((void**)&pWr, g_Wr);
    cudaGetSymbolAddress((void**)&pZK, g_ZK);

    cudaFuncSetAttribute(wgemm, cudaFuncAttributeMaxDynamicSharedMemorySize, WG_TOTAL);
    cudaFuncSetAttribute(lstm_persist7, cudaFuncAttributeMaxDynamicSharedMemorySize, PS_TOTAL);

    // 1. merged prep (also resets g_count each replay)
    prep_all<<<PREP_BLOCKS, 256>>>(X, h0, c0, W_emb, W_out, W_k, W_r);

    // 2. E = relu(X @ W_emb + b_emb) -> fp16
    {
        dim3 grid(1024 / 128, MROWS / 128);
        wgemm<<<grid, 256, WG_TOTAL>>>(pXh, pWemb, b_emb, nullptr, pEh, 1024, 0);
    }
    // 3. ZK = E @ W_k + b_r (fp32, permuted cols)
    {
        dim3 grid(4096 / 128, MROWS / 128);
        wgemm<<<grid, 256, WG_TOTAL>>>(pEh, pWk, b_r, pZK, nullptr, 4096, 1);
    }

    // 4. recurrence: persistent, fp16 1-term, chunk-128, W in SMEM
    lstm_persist7<<<NCTA, 512, PS_TOTAL>>>(pWr);

    // 5. OUT = H @ W_out + b_out, scattered to [b][t][:]
    {
        dim3 grid(1024 / 128, MROWS / 128);
        wgemm<<<grid, 256, WG_TOTAL>>>(pHhi + (size_t)BSZ * UN, pWout, b_out,
                                       (float*)d_out, nullptr, 1024, 2);
    }
}

// round 17
// speedup vs baseline: 1.1871x; 1.1871x over previous
#include <cuda_runtime.h>
#include <cuda_fp16.h>
#include <mma.h>
#include <cstdint>

using namespace nvcuda;

#define BSZ 128
#define TN  512
#define UN  1024
#define MROWS (TN * BSZ)   // 65536
#define NCTA 128

// ---------------- scratch (static device globals) ----------------
__device__ __half g_Xh [(size_t)MROWS * UN];
__device__ __half g_Eh [(size_t)MROWS * UN];
__device__ float  g_ZK [(size_t)MROWS * 4 * UN];   // permuted cols p=u*4+g
__device__ float  g_C  [(size_t)BSZ * UN];
__device__ __half g_Hhi[(size_t)(TN + 1) * BSZ * UN];
__device__ __half g_Wemb[(size_t)UN * UN];
__device__ __half g_Wout[(size_t)UN * UN];
__device__ __half g_Wk  [(size_t)UN * 4 * UN];     // permuted cols
__device__ __half g_Wr  [(size_t)UN * 4 * UN];     // permuted cols
__device__ int    g_flag[NCTA];                     // per-CTA step progress

struct __align__(8) H4 { __half v[4]; };

__device__ __forceinline__ void cp16(uint32_t dst, const void* src) {
    asm volatile("cp.async.cg.shared.global [%0], [%1], 16;" :: "r"(dst), "l"(src));
}
__device__ __forceinline__ void cp_commit() { asm volatile("cp.async.commit_group;"); }
template<int N> __device__ __forceinline__ void cp_wait() {
    asm volatile("cp.async.wait_group %0;" :: "n"(N));
}
__device__ __forceinline__ int ld_acq(const int* p) {
    int v;
    asm volatile("ld.global.acquire.gpu.b32 %0, [%1];" : "=r"(v) : "l"(p) : "memory");
    return v;
}
__device__ __forceinline__ void st_rel(int* p, int v) {
    asm volatile("st.global.release.gpu.b32 [%0], %1;" :: "l"(p), "r"(v) : "memory");
}

// ---------------- merged prep kernel ----------------
// [0,16384) X->fp16 (16 elems/thread) | [16384,16896) init_state |
// [16896,17920) W_emb | [17920,18944) W_out | [18944,23040) W_k perm | [23040,27136) W_r perm
#define PREP_ST0   16384
#define PREP_WE0   16896
#define PREP_WO0   17920
#define PREP_WK0   18944
#define PREP_WR0   23040
#define PREP_BLOCKS 27136

__global__ __launch_bounds__(256) void prep_all(
    const float* __restrict__ X, const float* __restrict__ h0, const float* __restrict__ c0,
    const float* __restrict__ W_emb, const float* __restrict__ W_out,
    const float* __restrict__ W_k, const float* __restrict__ W_r)
{
    const int b = blockIdx.x, tid = threadIdx.x;
    if (b < PREP_ST0) {                    // X -> fp16, 16 elems/thread
        size_t e = ((size_t)b * 256 + tid) * 16;
        size_t r = e >> 10;
        int k = (int)(e & 1023);
        int bb = (int)(r & 127), t = (int)(r >> 7);
        const float* src = X + ((size_t)bb * 513 + (size_t)t) * 1024 + k;
        float4 v0 = *(const float4*)(src);
        float4 v1 = *(const float4*)(src + 4);
        float4 v2 = *(const float4*)(src + 8);
        float4 v3 = *(const float4*)(src + 12);
        H4 h[4];
        h[0].v[0] = __float2half_rn(v0.x); h[0].v[1] = __float2half_rn(v0.y);
        h[0].v[2] = __float2half_rn(v0.z); h[0].v[3] = __float2half_rn(v0.w);
        h[1].v[0] = __float2half_rn(v1.x); h[1].v[1] = __float2half_rn(v1.y);
        h[1].v[2] = __float2half_rn(v1.z); h[1].v[3] = __float2half_rn(v1.w);
        h[2].v[0] = __float2half_rn(v2.x); h[2].v[1] = __float2half_rn(v2.y);
        h[2].v[2] = __float2half_rn(v2.z); h[2].v[3] = __float2half_rn(v2.w);
        h[3].v[0] = __float2half_rn(v3.x); h[3].v[1] = __float2half_rn(v3.y);
        h[3].v[2] = __float2half_rn(v3.z); h[3].v[3] = __float2half_rn(v3.w);
        *(int4*)(g_Xh + e)     = *(int4*)&h[0];
        *(int4*)(g_Xh + e + 8) = *(int4*)&h[2];
    } else if (b < PREP_WE0) {             // init_state (+ flag reset for replay determinism)
        int i = (b - PREP_ST0) * 256 + tid;
        if (b == PREP_ST0 && tid < NCTA) g_flag[tid] = 0;
        g_C[i] = c0[i];
        g_Hhi[i] = __float2half_rn(h0[i]);
    } else if (b < PREP_WK0) {             // W_emb / W_out -> fp16
        int isout = (b >= PREP_WO0);
        const float* W = isout ? W_out : W_emb;
        __half* dst = isout ? g_Wout : g_Wemb;
        size_t q = (size_t)(b - (isout ? PREP_WO0 : PREP_WE0)) * 256 + tid;
        size_t e = q * 4;
        float4 v = *(const float4*)(W + e);
        H4 h;
        h.v[0] = __float2half_rn(v.x); h.v[1] = __float2half_rn(v.y);
        h.v[2] = __float2half_rn(v.z); h.v[3] = __float2half_rn(v.w);
        *(H4*)(dst + e) = h;
    } else {                               // W_k / W_r permuted -> fp16
        int isr = (b >= PREP_WR0);
        const float* W = isr ? W_r : W_k;
        __half* dst = isr ? g_Wr : g_Wk;
        size_t q = (size_t)(b - (isr ? PREP_WR0 : PREP_WK0)) * 256 + tid;
        int row = (int)(q >> 10);
        int qc = (int)(q & 1023);
        const float* src = W + (size_t)row * 4096 + qc;
        H4 h;
        h.v[0] = __float2half_rn(src[0]);
        h.v[1] = __float2half_rn(src[1024]);
        h.v[2] = __float2half_rn(src[2048]);
        h.v[3] = __float2half_rn(src[3072]);
        *(H4*)(dst + (size_t)row * 4096 + (size_t)qc * 4) = h;
    }
}

// ---------------- fp16 1-term wmma GEMM, 2-buffer cp.async pipeline (unchanged) ----------------
#define WG_BUF   18944
#define WG_BIAS  37888
#define WG_TOTAL 46080

__global__ __launch_bounds__(256) void wgemm(
    const __half* __restrict__ A, const __half* __restrict__ B,
    const float* __restrict__ bias, float* __restrict__ D,
    __half* __restrict__ Dh,
    int N, int mode)
{
    extern __shared__ char sm[];
    const uint32_t smb = (uint32_t)__cvta_generic_to_shared(sm);

    const int tid = threadIdx.x;
    const int n0 = blockIdx.x * 128, m0 = blockIdx.y * 128;
    const int wid = tid >> 5, lane = tid & 31;
    const int wm = wid & 3, wn = wid >> 2;

    float (*sbias)[128] = (float (*)[128])(sm + WG_BIAS);
    for (int i = tid; i < 2048; i += 256) {
        int col = i & 127;
        int p = n0 + col;
        float bv = (mode == 1) ? bias[(p & 3) * 1024 + (p >> 2)] : bias[p];
        sbias[i >> 7][col] = bv;
    }
    __syncthreads();

    wmma::fragment<wmma::accumulator, 16, 16, 16, float> acc[2][4];
#pragma unroll
    for (int i = 0; i < 2; i++)
#pragma unroll
        for (int j = 0; j < 4; j++)
            wmma::load_matrix_sync(acc[i][j], &sbias[0][wn * 64 + j * 16], 128, wmma::mem_row_major);
    __syncthreads();

    const int arow = tid >> 1, aseg = (tid & 1) * 16;
    const int brow = tid >> 3, bseg = (tid & 7) * 16;

    auto issue = [&](int c) {
        uint32_t base = smb + (uint32_t)(c & 1) * WG_BUF;
        int k0 = c * 32;
        uint32_t ad = base + (uint32_t)(arow * 40 + aseg) * 2;
        const __half* ap = A + (size_t)(m0 + arow) * 1024 + k0 + aseg;
        cp16(ad,      ap);
        cp16(ad + 16, ap + 8);
        uint32_t bd = base + 10240 + (uint32_t)(brow * 136 + bseg) * 2;
        const __half* bp = B + (size_t)(k0 + brow) * N + n0 + bseg;
        cp16(bd,      bp);
        cp16(bd + 16, bp + 8);
        cp_commit();
    };

    issue(0);
    for (int c = 0; c < 32; c++) {
        cp_wait<0>();
        __syncthreads();
        if (c + 1 < 32) issue(c + 1);

        char* bufp = sm + (c & 1) * WG_BUF;
        __half (*sA)[40]  = (__half (*)[40])(bufp);
        __half (*sB)[136] = (__half (*)[136])(bufp + 10240);

#pragma unroll
        for (int kk = 0; kk < 32; kk += 16) {
            wmma::fragment<wmma::matrix_a, 16, 16, 16, __half, wmma::row_major> ah[2];
            wmma::fragment<wmma::matrix_b, 16, 16, 16, __half, wmma::row_major> bh[4];
#pragma unroll
            for (int i = 0; i < 2; i++)
                wmma::load_matrix_sync(ah[i], &sA[wm * 32 + i * 16][kk], 40);
#pragma unroll
            for (int j = 0; j < 4; j++)
                wmma::load_matrix_sync(bh[j], &sB[kk][wn * 64 + j * 16], 136);
#pragma unroll
            for (int i = 0; i < 2; i++)
#pragma unroll
                for (int j = 0; j < 4; j++)
                    wmma::mma_sync(acc[i][j], ah[i], bh[j], acc[i][j]);
        }
    }

    if (mode == 0) {
        float (*stage)[16] = (float (*)[16])((float*)(sm + WG_BIAS) + wid * 256);
        __syncthreads();
#pragma unroll
        for (int i = 0; i < 2; i++)
#pragma unroll
            for (int j = 0; j < 4; j++) {
                for (int e = 0; e < acc[i][j].num_elements; e++)
                    acc[i][j].x[e] = fmaxf(acc[i][j].x[e], 0.f);
                wmma::store_matrix_sync(&stage[0][0], acc[i][j], 16, wmma::mem_row_major);
                __syncwarp();
                int r = lane & 15, c8 = (lane >> 4) * 8;
                size_t row = (size_t)(m0 + wm * 32 + i * 16 + r);
                size_t off = row * 1024 + (n0 + wn * 64 + j * 16 + c8);
                H4 h0v, h1v;
#pragma unroll
                for (int e = 0; e < 4; e++) h0v.v[e] = __float2half_rn(stage[r][c8 + e]);
#pragma unroll
                for (int e = 0; e < 4; e++) h1v.v[e] = __float2half_rn(stage[r][c8 + 4 + e]);
                *(H4*)(Dh + off)     = h0v;
                *(H4*)(Dh + off + 4) = h1v;
                __syncwarp();
            }
        return;
    }

#pragma unroll
    for (int i = 0; i < 2; i++)
#pragma unroll
        for (int j = 0; j < 4; j++) {
            int col = n0 + wn * 64 + j * 16;
            if (mode == 2) {
                int t = m0 >> 7;
                int b = wm * 32 + i * 16;
                float* p = D + (size_t)t * 1024 + (size_t)b * ((size_t)TN * 1024) + col;
                wmma::store_matrix_sync(p, acc[i][j], (unsigned)(TN * 1024), wmma::mem_row_major);
            } else {
                int row = m0 + wm * 32 + i * 16;
                wmma::store_matrix_sync(D + (size_t)row * N + col, acc[i][j], N, wmma::mem_row_major);
            }
        }
}

// ---------------- persistent recurrence: fp16 1-term, K-chunk 64 (R15 config),
// fine-grained producer/consumer flags instead of a global barrier ----------------
// Chunk c of step t reads H units [64c, 64c+64) = outputs of CTAs 8c..8c+7 at step t-1.
#define PS_WH 0
#define PS_A  81920
#define PS_ABUF 18432
#define PS_TOTAL (81920 + 3 * PS_ABUF)    // 137216

__global__ __launch_bounds__(512, 1) void lstm_persist8(const __half* __restrict__ W_g)
{
    extern __shared__ char sm[];
    const uint32_t smb = (uint32_t)__cvta_generic_to_shared(sm);
    const int tid = threadIdx.x, wid = tid >> 5;
    const int bx = blockIdx.x;
    const int n0g = bx * 32;
    const int g = wid >> 3, w8 = wid & 7;
    const int wm = w8 >> 1, wn = w8 & 1;

    for (int i = tid; i < 4096; i += 512) {
        int row = i >> 2, seg = (i & 3) * 8;
        cp16(smb + PS_WH + (uint32_t)(row * 40 + seg) * 2, W_g + (size_t)row * 4096 + n0g + seg);
    }
    cp_commit(); cp_wait<0>();
    __syncthreads();

    __half (*WH)[40] = (__half (*)[40])(sm + PS_WH);

    const int m = tid & 127, grp = tid >> 7;
    const int pc = grp * 8;
    float cv[2];
    {
        float2 c2 = *(const float2*)(g_C + (size_t)m * UN + bx * 8 + grp * 2);
        cv[0] = c2.x; cv[1] = c2.y;
    }
    const int arow = tid >> 2, aseg = (tid & 3) * 16;

    for (int t = 0; t < TN; t++) {
        const __half* __restrict__ Hhi = g_Hhi + (size_t)t * (BSZ * UN);

        float zkf[8];
        {
            const float* zk = g_ZK + ((size_t)t * BSZ + m) * 4096 + n0g + pc;
            float4 v0 = *(const float4*)(zk);
            float4 v1 = *(const float4*)(zk + 4);
            zkf[0] = v0.x; zkf[1] = v0.y; zkf[2] = v0.z; zkf[3] = v0.w;
            zkf[4] = v1.x; zkf[5] = v1.y; zkf[6] = v1.z; zkf[7] = v1.w;
        }

        auto issueA = [&](int chunk) {
            int buf = chunk % 3;
            uint32_t ad = smb + PS_A + buf * PS_ABUF + (uint32_t)(arow * 72 + aseg) * 2;
            const __half* src = Hhi + (size_t)arow * 1024 + chunk * 64 + aseg;
            cp16(ad,      src);
            cp16(ad + 16, src + 8);
            cp_commit();
        };

        wmma::fragment<wmma::accumulator, 16, 16, 16, float> a0[2];
        wmma::fill_fragment(a0[0], 0.f);
        wmma::fill_fragment(a0[1], 0.f);

        // wait for producers of chunks 0 and 1 (flags 0..15), then prologue
        if (tid < 16) {
            while (ld_acq(&g_flag[tid]) < t) __nanosleep(32);
        }
        __syncthreads();
        issueA(0); issueA(1);

        for (int c = 0; c < 16; c++) {
            if (c < 15) cp_wait<1>(); else cp_wait<0>();
            // wait for producers of chunk c+2 before issuing it
            if (c + 2 < 16 && tid < 8) {
                while (ld_acq(&g_flag[(c + 2) * 8 + tid]) < t) __nanosleep(32);
            }
            __syncthreads();
            if (c + 2 < 16) issueA(c + 2);

            int buf = c % 3;
            __half (*Ah)[72] = (__half (*)[72])(sm + PS_A + buf * PS_ABUF);

#pragma unroll
            for (int s = 0; s < 2; s++) {
                const int kkg = c * 64 + g * 32 + s * 16;
                const int ka  = g * 32 + s * 16;
                wmma::fragment<wmma::matrix_b, 16, 16, 16, __half, wmma::row_major> bh;
                wmma::fragment<wmma::matrix_a, 16, 16, 16, __half, wmma::row_major> ah0, ah1;
                wmma::load_matrix_sync(bh, &WH[kkg][wn * 16], 40);
                wmma::load_matrix_sync(ah0, &Ah[wm * 32][ka], 72);
                wmma::load_matrix_sync(ah1, &Ah[wm * 32 + 16][ka], 72);
                wmma::mma_sync(a0[0], ah0, bh, a0[0]);
                wmma::mma_sync(a0[1], ah1, bh, a0[1]);
            }
        }

        // partial z per K-group -> two smem buffers (overlay A buffers 0 and 1)
        __syncthreads();
        float (*zp)[36] = (float (*)[36])(sm + PS_A + g * 18432);
#pragma unroll
        for (int i = 0; i < 2; i++)
            wmma::store_matrix_sync(&zp[wm * 32 + i * 16][wn * 16], a0[i], 36, wmma::mem_row_major);
        __syncthreads();

        float (*z0)[36] = (float (*)[36])(sm + PS_A);
        float (*z1)[36] = (float (*)[36])(sm + PS_A + 18432);
        __half2 hh2;
#pragma unroll
        for (int e = 0; e < 2; e++) {
            float zi = z0[m][pc + e * 4 + 0] + z1[m][pc + e * 4 + 0] + zkf[e * 4 + 0];
            float zf = z0[m][pc + e * 4 + 1] + z1[m][pc + e * 4 + 1] + zkf[e * 4 + 1];
            float zg = z0[m][pc + e * 4 + 2] + z1[m][pc + e * 4 + 2] + zkf[e * 4 + 2];
            float zo = z0[m][pc + e * 4 + 3] + z1[m][pc + e * 4 + 3] + zkf[e * 4 + 3];
            float si = 1.f / (1.f + __expf(-zi));
            float sf = 1.f / (1.f + __expf(-zf));
            float so = 1.f / (1.f + __expf(-zo));
            float cn = sf * cv[e] + si * tanhf(zg);
            float hn = so * tanhf(cn);
            cv[e] = cn;
            __half h = __float2half_rn(hn);
            if (e == 0) hh2.x = h; else hh2.y = h;
        }
        size_t ho = (size_t)(t + 1) * (BSZ * UN) + (size_t)m * UN + bx * 8 + grp * 2;
        *(__half2*)(g_Hhi + ho) = hh2;

        // publish: all H writes of this CTA done -> flag = t+1
        __syncthreads();
        if (tid == 0) {
            __threadfence();
            st_rel(&g_flag[bx], t + 1);
        }
    }
}

// ---------------- host ----------------
extern "C" void kernel_launch(void* const* d_in, const int* in_sizes, int n_in,
                              void* d_out, int out_size)
{
    const float* h0    = (const float*)d_in[0];
    const float* c0    = (const float*)d_in[1];
    const float* X     = (const float*)d_in[2];
    const float* W_emb = (const float*)d_in[3];
    const float* b_emb = (const float*)d_in[4];
    const float* W_k   = (const float*)d_in[5];
    const float* W_r   = (const float*)d_in[6];
    const float* b_r   = (const float*)d_in[7];
    const float* W_out = (const float*)d_in[8];
    const float* b_out = (const float*)d_in[9];
    (void)in_sizes; (void)n_in; (void)out_size;

    __half *pXh, *pEh, *pHhi, *pWemb, *pWout, *pWk, *pWr;
    float *pZK;
    cudaGetSymbolAddress((void**)&pXh, g_Xh);
    cudaGetSymbolAddress((void**)&pEh, g_Eh);
    cudaGetSymbolAddress((void**)&pHhi, g_Hhi);
    cudaGetSymbolAddress((void**)&pWemb, g_Wemb);
    cudaGetSymbolAddress((void**)&pWout, g_Wout);
    cudaGetSymbolAddress((void**)&pWk, g_Wk);
    cudaGetSymbolAddress((void**)&pWr, g_Wr);
    cudaGetSymbolAddress((void**)&pZK, g_ZK);

    cudaFuncSetAttribute(wgemm, cudaFuncAttributeMaxDynamicSharedMemorySize, WG_TOTAL);
    cudaFuncSetAttribute(lstm_persist8, cudaFuncAttributeMaxDynamicSharedMemorySize, PS_TOTAL);

    // 1. merged prep (resets flags each replay)
    prep_all<<<PREP_BLOCKS, 256>>>(X, h0, c0, W_emb, W_out, W_k, W_r);

    // 2. E = relu(X @ W_emb + b_emb) -> fp16
    {
        dim3 grid(1024 / 128, MROWS / 128);
        wgemm<<<grid, 256, WG_TOTAL>>>(pXh, pWemb, b_emb, nullptr, pEh, 1024, 0);
    }
    // 3. ZK = E @ W_k + b_r (fp32, permuted cols)
    {
        dim3 grid(4096 / 128, MROWS / 128);
        wgemm<<<grid, 256, WG_TOTAL>>>(pEh, pWk, b_r, pZK, nullptr, 4096, 1);
    }

    // 4. recurrence: persistent, fp16 1-term, chunk-64, flag-pipelined steps
    lstm_persist8<<<NCTA, 512, PS_TOTAL>>>(pWr);

    // 5. OUT = H @ W_out + b_out, scattered to [b][t][:]
    {
        dim3 grid(1024 / 128, MROWS / 128);
        wgemm<<<grid, 256, WG_TOTAL>>>(pHhi + (size_t)BSZ * UN, pWout, b_out,
                                       (float*)d_out, nullptr, 1024, 2);
    }
}